// round 5
// baseline (speedup 1.0000x reference)
#include <cuda_runtime.h>

// ---------------------------------------------------------------------------
// Routing_2259152797848: capsule routing
// R5: SEL-free XOR-permuted butterfly tree + packed f32x2 (FFMA2/FADD2/FMUL2).
// ---------------------------------------------------------------------------

#define MAXN 50016
#define D    128
#define CH   8
#define KD   16
#define M    32

typedef unsigned long long u64;

__device__ float g_z[(size_t)(MAXN + 1) * D];
__device__ int   g_is64;

// --- packed f32x2 helpers ----------------------------------------------------
__device__ __forceinline__ u64 pk(float a, float b) {
    u64 r; asm("mov.b64 %0,{%1,%2};" : "=l"(r) : "f"(a), "f"(b)); return r;
}
__device__ __forceinline__ float plo(u64 v) {
    float a; asm("{.reg .f32 h; mov.b64 {%0,h}, %1;}" : "=f"(a) : "l"(v)); return a;
}
__device__ __forceinline__ float phi(u64 v) {
    float b; asm("{.reg .f32 l; mov.b64 {l,%0}, %1;}" : "=f"(b) : "l"(v)); return b;
}
__device__ __forceinline__ u64 add2(u64 a, u64 b) {
    u64 r; asm("add.rn.f32x2 %0,%1,%2;" : "=l"(r) : "l"(a), "l"(b)); return r;
}
__device__ __forceinline__ u64 mul2(u64 a, u64 b) {
    u64 r; asm("mul.rn.f32x2 %0,%1,%2;" : "=l"(r) : "l"(a), "l"(b)); return r;
}
__device__ __forceinline__ u64 fma2(u64 a, u64 b, u64 c) {
    u64 r; asm("fma.rn.f32x2 %0,%1,%2,%3;" : "=l"(r) : "l"(a), "l"(b), "l"(c)); return r;
}
__device__ __forceinline__ u64 shfl64(u64 v, int m) {
    unsigned lo, hi;
    asm("mov.b64 {%0,%1}, %2;" : "=r"(lo), "=r"(hi) : "l"(v));
    lo = __shfl_xor_sync(0xffffffffu, lo, m);
    hi = __shfl_xor_sync(0xffffffffu, hi, m);
    u64 r; asm("mov.b64 %0,{%1,%2};" : "=l"(r) : "r"(lo), "r"(hi)); return r;
}

__global__ void k_detect(const int* __restrict__ w) {
    if (threadIdx.x == 0) {
        int any = 0;
        #pragma unroll 8
        for (int i = 0; i < 128; i++) any |= w[2 * i + 1];
        g_is64 = (any == 0) ? 1 : 0;
    }
}

__global__ void k_zero(int n) {
    g_z[(size_t)n * D + threadIdx.x] = 0.0f;
}

// --- FC + relu + per-capsule normalize ---------------------------------------
__global__ void k_fc(const float* __restrict__ x, const float* __restrict__ W,
                     const float* __restrict__ b, int n) {
    extern __shared__ float smem[];
    float* w_s = smem;             // [128][132]
    float* x_s = smem + 128 * 132; // [32][128]

    const int t = threadIdx.x;
    const int r0 = blockIdx.x * 32;

    const float4* W4 = (const float4*)W;
    float4* ws4 = (float4*)w_s;
    #pragma unroll
    for (int i = 0; i < 32; i++) {
        int idx4 = t + 128 * i;
        int j = idx4 >> 5, kk = idx4 & 31;
        ws4[j * 33 + kk] = W4[idx4];
    }
    const float4* X4 = (const float4*)x;
    float4* xs4 = (float4*)x_s;
    #pragma unroll
    for (int i = 0; i < 8; i++) {
        int idx4 = t + 128 * i;
        int r = idx4 >> 5, kk = idx4 & 31;
        float4 v = make_float4(0.f, 0.f, 0.f, 0.f);
        if (r0 + r < n) v = X4[(size_t)(r0 + r) * 32 + kk];
        xs4[r * 32 + kk] = v;
    }
    __syncthreads();

    const int tx = t & 31;
    const int ty = t >> 5;

    float acc[8][4];
    #pragma unroll
    for (int rr = 0; rr < 8; rr++)
        #pragma unroll
        for (int cc = 0; cc < 4; cc++) acc[rr][cc] = 0.f;

    #pragma unroll 4
    for (int k4 = 0; k4 < 32; k4++) {
        float4 wv[4];
        #pragma unroll
        for (int cc = 0; cc < 4; cc++) wv[cc] = ws4[(tx + 32 * cc) * 33 + k4];
        float4 xr[8];
        #pragma unroll
        for (int rr = 0; rr < 8; rr++) xr[rr] = xs4[(ty + 4 * rr) * 32 + k4];
        #pragma unroll
        for (int rr = 0; rr < 8; rr++)
            #pragma unroll
            for (int cc = 0; cc < 4; cc++) {
                acc[rr][cc] = fmaf(xr[rr].x, wv[cc].x, acc[rr][cc]);
                acc[rr][cc] = fmaf(xr[rr].y, wv[cc].y, acc[rr][cc]);
                acc[rr][cc] = fmaf(xr[rr].z, wv[cc].z, acc[rr][cc]);
                acc[rr][cc] = fmaf(xr[rr].w, wv[cc].w, acc[rr][cc]);
            }
    }

    float bv[4];
    #pragma unroll
    for (int cc = 0; cc < 4; cc++) bv[cc] = b[tx + 32 * cc];

    #pragma unroll
    for (int rr = 0; rr < 8; rr++) {
        int row = r0 + ty + 4 * rr;
        #pragma unroll
        for (int cc = 0; cc < 4; cc++) {
            float v = fmaxf(acc[rr][cc] + bv[cc], 0.f);
            float s = v * v;
            s += __shfl_xor_sync(0xffffffffu, s, 1);
            s += __shfl_xor_sync(0xffffffffu, s, 2);
            s += __shfl_xor_sync(0xffffffffu, s, 4);
            s += __shfl_xor_sync(0xffffffffu, s, 8);
            float inv = rsqrtf(fmaxf(s, 1e-24f));
            if (row < n) g_z[(size_t)row * D + tx + 32 * cc] = v * inv;
        }
    }
}

// --- routing: 256 threads = 2 independent nodes -------------------------------
// Thread (c = tl>>4, g = tl&15) keeps neighbor PAIR q at register j = q ^ g
// (pair q = values for m = 2q, 2q+1, element (c, k=g)). Butterfly stage mask b:
//   new[j] = v[j] + shfl_xor(v[j^b], b)  for j with bit(b)==0   — NO selects.
// After masks 1,2,4,8 register 0 holds (d[2g], d[2g+1]).
__global__ __launch_bounds__(256) void k_route(const void* __restrict__ nid_raw,
                                               float* __restrict__ out, int n) {
    __shared__ float stage[2][128 * 33];              // self-permute scratch
    __shared__ __align__(16) float d_s[2][CH * 40];   // d_s[c*40 + m] (pairs)
    __shared__ __align__(16) float ps[2][CH * 36];    // ps[c*36 + m]
    __shared__ int ids[2][M];

    const int t   = threadIdx.x;
    const int grp = t >> 7;
    const int tl  = t & 127;
    const int bid = 1 + grp;
    const int node = blockIdx.x * 2 + grp;
    if (node >= n) return;
    const int is64 = g_is64;

    if (tl < M) {
        long long id;
        if (is64) id = ((const long long*)nid_raw)[(size_t)node * M + tl];
        else      id = (long long)((const int*)nid_raw)[(size_t)node * M + tl];
        ids[grp][tl] = (int)id;
    }
    const float xc = g_z[(size_t)node * D + tl];
    asm volatile("bar.sync %0, %1;" :: "r"(bid), "r"(128) : "memory");

    // coalesced gather into this thread's private stage row (no cross-thread use)
    float* stg = &stage[grp][tl * 33];
    #pragma unroll
    for (int m = 0; m < M; m++)
        stg[m] = g_z[(size_t)ids[grp][m] * D + tl];

    const int g = tl & 15;          // k-lane within channel
    const int c = tl >> 4;          // channel
    const int m0 = tl >> 3;         // softmax identity
    const int cA = tl & 7;

    // self-permuted packed neighbor pairs: nbrp[j] = (nb[2(j^g)], nb[2(j^g)+1])
    u64 nbrp[16];
    #pragma unroll
    for (int j = 0; j < 16; j++) {
        int q2 = 2 * (j ^ g);
        nbrp[j] = pk(stg[q2], stg[q2 + 1]);
    }

    float u_val = xc;
    float acc;

    for (int it = 0; it < 3; it++) {
        // ---- SEL-free packed butterfly: d[m] = sum_k u[c,k]*nb[m,c,k] ----
        u64 u2 = pk(u_val, u_val);
        u64 s1[8];
        #pragma unroll
        for (int j = 0; j < 8; j++)
            s1[j] = add2(mul2(u2, nbrp[2 * j]),
                         shfl64(mul2(u2, nbrp[2 * j + 1]), 1));
        u64 s2[4];
        #pragma unroll
        for (int j = 0; j < 4; j++)
            s2[j] = add2(s1[2 * j], shfl64(s1[2 * j + 1], 2));
        u64 s3[2];
        #pragma unroll
        for (int j = 0; j < 2; j++)
            s3[j] = add2(s2[2 * j], shfl64(s2[2 * j + 1], 4));
        u64 s4 = add2(s3[0], shfl64(s3[1], 8));

        // |d| <= 1 (unit capsules): exp safe without max-subtraction
        float e0 = __expf(plo(s4));
        float e1 = __expf(phi(s4));
        *(u64*)&d_s[grp][c * 40 + 2 * g] = pk(e0, e1);
        asm volatile("bar.sync %0, %1;" :: "r"(bid), "r"(128) : "memory");

        // ---- softmax over c (8 adjacent lanes), thread = (m0, cA) ----
        float f0 = d_s[grp][cA * 40 + m0];
        float f1 = d_s[grp][cA * 40 + m0 + 16];
        float sm0 = f0, sm1 = f1;
        sm0 += __shfl_xor_sync(0xffffffffu, sm0, 1);
        sm1 += __shfl_xor_sync(0xffffffffu, sm1, 1);
        sm0 += __shfl_xor_sync(0xffffffffu, sm0, 2);
        sm1 += __shfl_xor_sync(0xffffffffu, sm1, 2);
        sm0 += __shfl_xor_sync(0xffffffffu, sm0, 4);
        sm1 += __shfl_xor_sync(0xffffffffu, sm1, 4);
        ps[grp][cA * 36 + m0]      = __fdividef(f0, sm0);
        ps[grp][cA * 36 + m0 + 16] = __fdividef(f1, sm1);
        asm volatile("bar.sync %0, %1;" :: "r"(bid), "r"(128) : "memory");

        // ---- phase B: u[c,k] = x_caps + sum_m p[m,c]*nb[m,c,k] (packed) ----
        u64 acc2 = pk(xc, 0.f);
        #pragma unroll
        for (int j = 0; j < 16; j++) {
            u64 pp = *(const u64*)&ps[grp][c * 36 + 2 * (j ^ g)];
            acc2 = fma2(pp, nbrp[j], acc2);
        }
        acc = plo(acc2) + phi(acc2);

        if (it < 2) {
            float sq = acc * acc;
            sq += __shfl_xor_sync(0xffffffffu, sq, 1);
            sq += __shfl_xor_sync(0xffffffffu, sq, 2);
            sq += __shfl_xor_sync(0xffffffffu, sq, 4);
            sq += __shfl_xor_sync(0xffffffffu, sq, 8);
            u_val = acc * rsqrtf(fmaxf(sq, 1e-24f));
        } else {
            out[(size_t)node * D + tl] = acc;
        }
    }
}

// ---------------------------------------------------------------------------
extern "C" void kernel_launch(void* const* d_in, const int* in_sizes, int n_in,
                              void* d_out, int out_size) {
    const float* x = (const float*)d_in[0];
    const float* W = (const float*)d_in[1];
    const float* b = (const float*)d_in[2];
    const void*  nid = d_in[3];
    float* out = (float*)d_out;

    int n = in_sizes[0] / D;

    static const size_t FC_SMEM = (size_t)(128 * 132 + 32 * 128) * sizeof(float);
    cudaFuncSetAttribute(k_fc, cudaFuncAttributeMaxDynamicSharedMemorySize,
                         (int)FC_SMEM);

    k_detect<<<1, 32>>>((const int*)nid);
    k_zero<<<1, D>>>(n);
    int nblk = (n + 31) / 32;
    k_fc<<<nblk, 128, FC_SMEM>>>(x, W, b, n);
    k_route<<<(n + 1) / 2, 256>>>(nid, out, n);
}

// round 6
// speedup vs baseline: 1.3625x; 1.3625x over previous
#include <cuda_runtime.h>

// ---------------------------------------------------------------------------
// Routing_2259152797848: capsule routing
// R6: R4 base + SEL-free XOR-permuted scalar trees (local-memory self-permute).
// ---------------------------------------------------------------------------

#define MAXN 50016
#define D    128
#define CH   8
#define KD   16
#define M    32

__device__ float g_z[(size_t)(MAXN + 1) * D];
__device__ int   g_is64;

__global__ void k_detect(const int* __restrict__ w) {
    if (threadIdx.x == 0) {
        int any = 0;
        #pragma unroll 8
        for (int i = 0; i < 128; i++) any |= w[2 * i + 1];
        g_is64 = (any == 0) ? 1 : 0;
    }
}

__global__ void k_zero(int n) {
    g_z[(size_t)n * D + threadIdx.x] = 0.0f;
}

// --- FC + relu + per-capsule normalize (unchanged from R4) --------------------
__global__ void k_fc(const float* __restrict__ x, const float* __restrict__ W,
                     const float* __restrict__ b, int n) {
    extern __shared__ float smem[];
    float* w_s = smem;             // [128][132]
    float* x_s = smem + 128 * 132; // [32][128]

    const int t = threadIdx.x;
    const int r0 = blockIdx.x * 32;

    const float4* W4 = (const float4*)W;
    float4* ws4 = (float4*)w_s;
    #pragma unroll
    for (int i = 0; i < 32; i++) {
        int idx4 = t + 128 * i;
        int j = idx4 >> 5, kk = idx4 & 31;
        ws4[j * 33 + kk] = W4[idx4];
    }
    const float4* X4 = (const float4*)x;
    float4* xs4 = (float4*)x_s;
    #pragma unroll
    for (int i = 0; i < 8; i++) {
        int idx4 = t + 128 * i;
        int r = idx4 >> 5, kk = idx4 & 31;
        float4 v = make_float4(0.f, 0.f, 0.f, 0.f);
        if (r0 + r < n) v = X4[(size_t)(r0 + r) * 32 + kk];
        xs4[r * 32 + kk] = v;
    }
    __syncthreads();

    const int tx = t & 31;
    const int ty = t >> 5;

    float acc[8][4];
    #pragma unroll
    for (int rr = 0; rr < 8; rr++)
        #pragma unroll
        for (int cc = 0; cc < 4; cc++) acc[rr][cc] = 0.f;

    #pragma unroll 4
    for (int k4 = 0; k4 < 32; k4++) {
        float4 wv[4];
        #pragma unroll
        for (int cc = 0; cc < 4; cc++) wv[cc] = ws4[(tx + 32 * cc) * 33 + k4];
        float4 xr[8];
        #pragma unroll
        for (int rr = 0; rr < 8; rr++) xr[rr] = xs4[(ty + 4 * rr) * 32 + k4];
        #pragma unroll
        for (int rr = 0; rr < 8; rr++)
            #pragma unroll
            for (int cc = 0; cc < 4; cc++) {
                acc[rr][cc] = fmaf(xr[rr].x, wv[cc].x, acc[rr][cc]);
                acc[rr][cc] = fmaf(xr[rr].y, wv[cc].y, acc[rr][cc]);
                acc[rr][cc] = fmaf(xr[rr].z, wv[cc].z, acc[rr][cc]);
                acc[rr][cc] = fmaf(xr[rr].w, wv[cc].w, acc[rr][cc]);
            }
    }

    float bv[4];
    #pragma unroll
    for (int cc = 0; cc < 4; cc++) bv[cc] = b[tx + 32 * cc];

    #pragma unroll
    for (int rr = 0; rr < 8; rr++) {
        int row = r0 + ty + 4 * rr;
        #pragma unroll
        for (int cc = 0; cc < 4; cc++) {
            float v = fmaxf(acc[rr][cc] + bv[cc], 0.f);
            float s = v * v;
            s += __shfl_xor_sync(0xffffffffu, s, 1);
            s += __shfl_xor_sync(0xffffffffu, s, 2);
            s += __shfl_xor_sync(0xffffffffu, s, 4);
            s += __shfl_xor_sync(0xffffffffu, s, 8);
            float inv = rsqrtf(fmaxf(s, 1e-24f));
            if (row < n) g_z[(size_t)row * D + tx + 32 * cc] = v * inv;
        }
    }
}

// --- routing: 256 threads = 2 independent nodes -------------------------------
// Thread (c = tl>>4, g = tl&15) keeps neighbor pair q = j^g at register slot j:
//   nbrA[j] = nb[2(j^g)][c][g],  nbrB[j] = nb[2(j^g)+1][c][g]
// Butterfly stage mask b: surviving slots have bit b == 0 (uniform across
// lanes -> NO selects):  new[i] = old[2i] + shfl_xor(old[2i+1], b).
// After masks 1,2,4,8 slot 0 holds (d[2g], d[2g+1]).
__global__ __launch_bounds__(256) void k_route(const void* __restrict__ nid_raw,
                                               float* __restrict__ out, int n) {
    __shared__ __align__(16) float d_s[2][CH * 40];   // d_s[c*40 + m] (pair writes)
    __shared__ __align__(16) float ps[2][CH * 36];    // ps[c*36 + m]
    __shared__ int ids[2][M];

    const int t   = threadIdx.x;
    const int grp = t >> 7;
    const int tl  = t & 127;
    const int bid = 1 + grp;
    const int node = blockIdx.x * 2 + grp;
    if (node >= n) return;
    const int is64 = g_is64;

    if (tl < M) {
        long long id;
        if (is64) id = ((const long long*)nid_raw)[(size_t)node * M + tl];
        else      id = (long long)((const int*)nid_raw)[(size_t)node * M + tl];
        ids[grp][tl] = (int)id;
    }
    const float xc = g_z[(size_t)node * D + tl];
    asm volatile("bar.sync %0, %1;" :: "r"(bid), "r"(128) : "memory");

    const int g = tl & 15;          // k-lane within channel
    const int c = tl >> 4;          // channel
    const int m0 = tl >> 3;         // softmax identity
    const int cA = tl & 7;

    // coalesced gather -> local-memory self-permute (volatile forces STL/LDL,
    // keeping SMEM footprint and register count unchanged)
    volatile float2 lv[16];
    #pragma unroll
    for (int q = 0; q < 16; q++) {
        float a = g_z[(size_t)ids[grp][2 * q]     * D + tl];
        float b = g_z[(size_t)ids[grp][2 * q + 1] * D + tl];
        lv[q].x = a; lv[q].y = b;
    }
    float nbrA[16], nbrB[16];
    #pragma unroll
    for (int j = 0; j < 16; j++) {
        int q = j ^ g;
        nbrA[j] = lv[q].x;
        nbrB[j] = lv[q].y;
    }

    float u_val = xc;
    float acc;

    for (int it = 0; it < 3; it++) {
        // ---- SEL-free scalar butterflies (even-m tree A, odd-m tree B) ----
        float a1[8], b1[8];
        #pragma unroll
        for (int i = 0; i < 8; i++) {
            a1[i] = u_val * nbrA[2 * i] +
                    __shfl_xor_sync(0xffffffffu, u_val * nbrA[2 * i + 1], 1);
            b1[i] = u_val * nbrB[2 * i] +
                    __shfl_xor_sync(0xffffffffu, u_val * nbrB[2 * i + 1], 1);
        }
        float a2[4], b2[4];
        #pragma unroll
        for (int i = 0; i < 4; i++) {
            a2[i] = a1[2 * i] + __shfl_xor_sync(0xffffffffu, a1[2 * i + 1], 2);
            b2[i] = b1[2 * i] + __shfl_xor_sync(0xffffffffu, b1[2 * i + 1], 2);
        }
        float a3[2], b3[2];
        #pragma unroll
        for (int i = 0; i < 2; i++) {
            a3[i] = a2[2 * i] + __shfl_xor_sync(0xffffffffu, a2[2 * i + 1], 4);
            b3[i] = b2[2 * i] + __shfl_xor_sync(0xffffffffu, b2[2 * i + 1], 4);
        }
        float dA = a3[0] + __shfl_xor_sync(0xffffffffu, a3[1], 8);  // d[2g]
        float dB = b3[0] + __shfl_xor_sync(0xffffffffu, b3[1], 8);  // d[2g+1]

        // |d| <= 1 (unit capsules): exp safe without max-subtraction
        float e0 = __expf(dA);
        float e1 = __expf(dB);
        *(float2*)&d_s[grp][c * 40 + 2 * g] = make_float2(e0, e1);
        asm volatile("bar.sync %0, %1;" :: "r"(bid), "r"(128) : "memory");

        // ---- softmax over c (8 adjacent lanes), thread = (m0, cA) ----
        float f0 = d_s[grp][cA * 40 + m0];
        float f1 = d_s[grp][cA * 40 + m0 + 16];
        float sm0 = f0, sm1 = f1;
        sm0 += __shfl_xor_sync(0xffffffffu, sm0, 1);
        sm1 += __shfl_xor_sync(0xffffffffu, sm1, 1);
        sm0 += __shfl_xor_sync(0xffffffffu, sm0, 2);
        sm1 += __shfl_xor_sync(0xffffffffu, sm1, 2);
        sm0 += __shfl_xor_sync(0xffffffffu, sm0, 4);
        sm1 += __shfl_xor_sync(0xffffffffu, sm1, 4);
        ps[grp][cA * 36 + m0]      = __fdividef(f0, sm0);
        ps[grp][cA * 36 + m0 + 16] = __fdividef(f1, sm1);
        asm volatile("bar.sync %0, %1;" :: "r"(bid), "r"(128) : "memory");

        // ---- phase B: u[c,k] = x_caps + sum_m p[m,c]*nb[m,c,k] ----
        acc = xc;
        #pragma unroll
        for (int j = 0; j < 16; j++) {
            float2 pp = *(const float2*)&ps[grp][c * 36 + 2 * (j ^ g)];
            acc = fmaf(pp.x, nbrA[j], acc);
            acc = fmaf(pp.y, nbrB[j], acc);
        }

        if (it < 2) {
            float sq = acc * acc;
            sq += __shfl_xor_sync(0xffffffffu, sq, 1);
            sq += __shfl_xor_sync(0xffffffffu, sq, 2);
            sq += __shfl_xor_sync(0xffffffffu, sq, 4);
            sq += __shfl_xor_sync(0xffffffffu, sq, 8);
            u_val = acc * rsqrtf(fmaxf(sq, 1e-24f));
        } else {
            out[(size_t)node * D + tl] = acc;
        }
    }
}

// ---------------------------------------------------------------------------
extern "C" void kernel_launch(void* const* d_in, const int* in_sizes, int n_in,
                              void* d_out, int out_size) {
    const float* x = (const float*)d_in[0];
    const float* W = (const float*)d_in[1];
    const float* b = (const float*)d_in[2];
    const void*  nid = d_in[3];
    float* out = (float*)d_out;

    int n = in_sizes[0] / D;

    static const size_t FC_SMEM = (size_t)(128 * 132 + 32 * 128) * sizeof(float);
    cudaFuncSetAttribute(k_fc, cudaFuncAttributeMaxDynamicSharedMemorySize,
                         (int)FC_SMEM);

    k_detect<<<1, 32>>>((const int*)nid);
    k_zero<<<1, D>>>(n);
    int nblk = (n + 31) / 32;
    k_fc<<<nblk, 128, FC_SMEM>>>(x, W, b, n);
    k_route<<<(n + 1) / 2, 256>>>(nid, out, n);
}